// round 2
// baseline (speedup 1.0000x reference)
#include <cuda_runtime.h>

#define N_NODES  10000
#define N_EDGES  640000
#define N_GRAPHS 64
#define F        128

// ---------------- scratch ----------------
__device__ int   g_deg_out[N_NODES];
__device__ int   g_deg_in [N_NODES];
__device__ float g_norm_src[N_NODES];
__device__ float g_norm_dst[N_NODES];
__device__ int   g_row_ptr[N_NODES + 1];
__device__ int   g_cursor [N_NODES];
__device__ int   g_csr    [N_EDGES];        // src ids grouped by dst
__device__ float g_y      [N_NODES * F];    // Y = (X @ W) * norm_src   (per layer)
__device__ float g_h1     [N_NODES * F];    // layer-1 activations
__device__ float g_gsum   [N_GRAPHS];
__device__ int   g_gcnt   [N_GRAPHS];

// ---------------- init / degrees ----------------
__global__ void k_init() {
    int i = blockIdx.x * blockDim.x + threadIdx.x;
    if (i < N_NODES) { g_deg_out[i] = 0; g_deg_in[i] = 0; }
}

__global__ void k_degree(const int* __restrict__ src, const int* __restrict__ dst) {
    int e = blockIdx.x * blockDim.x + threadIdx.x;
    if (e < N_EDGES) {
        atomicAdd(&g_deg_out[src[e]], 1);
        atomicAdd(&g_deg_in [dst[e]], 1);
    }
}

// ---------------- norms + graph counts + prefix scan (one block) ----------------
__global__ void k_norms_scan(const int* __restrict__ gids) {
    const int T = 256, C = 40;              // 256*40 = 10240 >= N_NODES
    __shared__ int s[T];
    __shared__ int cnt[N_GRAPHS];
    int t = threadIdx.x;
    if (t < N_GRAPHS) cnt[t] = 0;
    __syncthreads();

    int base = t * C;
    int local = 0;
    #pragma unroll
    for (int i = 0; i < C; i++) {
        int idx = base + i;
        if (idx < N_NODES) {
            g_norm_src[idx] = rsqrtf((float)max(g_deg_out[idx], 1));
            g_norm_dst[idx] = rsqrtf((float)max(g_deg_in [idx], 1));
            atomicAdd(&cnt[gids[idx]], 1);
            local += g_deg_in[idx];
        }
    }
    s[t] = local;
    __syncthreads();
    for (int off = 1; off < T; off <<= 1) {
        int v = (t >= off) ? s[t - off] : 0;
        __syncthreads();
        s[t] += v;
        __syncthreads();
    }
    int run = (t == 0) ? 0 : s[t - 1];
    for (int i = 0; i < C; i++) {
        int idx = base + i;
        if (idx < N_NODES) {
            g_row_ptr[idx] = run;
            g_cursor [idx] = run;
            run += g_deg_in[idx];
        }
    }
    if (t == T - 1) g_row_ptr[N_NODES] = run;
    if (t < N_GRAPHS) { g_gcnt[t] = cnt[t]; g_gsum[t] = 0.f; }
}

__global__ void k_scatter(const int* __restrict__ src, const int* __restrict__ dst) {
    int e = blockIdx.x * blockDim.x + threadIdx.x;
    if (e < N_EDGES) {
        int pos = atomicAdd(&g_cursor[dst[e]], 1);
        g_csr[pos] = src[e];
    }
}

// ---------------- GEMM: Y[n] = (X[n] @ W) * norm_src[n] ----------------
// warp-per-row; W stays L1-resident (only reused stream in this kernel),
// X is streamed once (evict-first), no gather pollution.
__global__ __launch_bounds__(256) void k_gemm(const float* __restrict__ X,
                                              const float* __restrict__ W,
                                              float* __restrict__ Y) {
    const int WARPS = 8;
    __shared__ float rowbuf[WARPS][F];
    int w    = threadIdx.x >> 5;
    int lane = threadIdx.x & 31;
    int n    = blockIdx.x * WARPS + w;
    if (n >= N_NODES) return;

    float4 xv = __ldcs((const float4*)X + n * 32 + lane);  // stream, evict-first
    rowbuf[w][lane * 4 + 0] = xv.x;
    rowbuf[w][lane * 4 + 1] = xv.y;
    rowbuf[w][lane * 4 + 2] = xv.z;
    rowbuf[w][lane * 4 + 3] = xv.w;
    __syncwarp();

    const float4* W4 = (const float4*)W;
    float ox = 0.f, oy = 0.f, oz = 0.f, ow = 0.f;
    #pragma unroll 16
    for (int k = 0; k < F; k++) {
        float av  = rowbuf[w][k];
        float4 wv = __ldg(W4 + k * 32 + lane);   // L1-resident
        ox += av * wv.x; oy += av * wv.y; oz += av * wv.z; ow += av * wv.w;
    }
    float ns = g_norm_src[n];
    ((float4*)Y)[n * 32 + lane] = make_float4(ox * ns, oy * ns, oz * ns, ow * ns);
}

// ---------------- aggregate: h[n] = relu(norm_dst[n]*sum_{s in N(n)} Y[s] + b) ----------------
template <bool FUSE_POOL>
__global__ __launch_bounds__(256) void k_agg(const float* __restrict__ Y,
                                             const float* __restrict__ b,
                                             float* __restrict__ hout,
                                             const float* __restrict__ Wd,
                                             const int*  __restrict__ gids) {
    const int WARPS = 8;
    int w    = threadIdx.x >> 5;
    int lane = threadIdx.x & 31;
    int n    = blockIdx.x * WARPS + w;
    if (n >= N_NODES) return;

    int beg = g_row_ptr[n], end = g_row_ptr[n + 1];
    const float4* Y4 = (const float4*)Y;

    float ax = 0.f, ay = 0.f, az = 0.f, aw = 0.f;
    int e = beg;
    for (; e + 8 <= end; e += 8) {
        int s0 = g_csr[e+0], s1 = g_csr[e+1], s2 = g_csr[e+2], s3 = g_csr[e+3];
        int s4 = g_csr[e+4], s5 = g_csr[e+5], s6 = g_csr[e+6], s7 = g_csr[e+7];
        float4 v0 = __ldcg(Y4 + s0 * 32 + lane);
        float4 v1 = __ldcg(Y4 + s1 * 32 + lane);
        float4 v2 = __ldcg(Y4 + s2 * 32 + lane);
        float4 v3 = __ldcg(Y4 + s3 * 32 + lane);
        float4 v4 = __ldcg(Y4 + s4 * 32 + lane);
        float4 v5 = __ldcg(Y4 + s5 * 32 + lane);
        float4 v6 = __ldcg(Y4 + s6 * 32 + lane);
        float4 v7 = __ldcg(Y4 + s7 * 32 + lane);
        ax += ((v0.x + v1.x) + (v2.x + v3.x)) + ((v4.x + v5.x) + (v6.x + v7.x));
        ay += ((v0.y + v1.y) + (v2.y + v3.y)) + ((v4.y + v5.y) + (v6.y + v7.y));
        az += ((v0.z + v1.z) + (v2.z + v3.z)) + ((v4.z + v5.z) + (v6.z + v7.z));
        aw += ((v0.w + v1.w) + (v2.w + v3.w)) + ((v4.w + v5.w) + (v6.w + v7.w));
    }
    for (; e < end; e++) {
        int s = g_csr[e];
        float4 v = __ldcg(Y4 + s * 32 + lane);
        ax += v.x; ay += v.y; az += v.z; aw += v.w;
    }

    float nd = g_norm_dst[n];
    float4 bv = ((const float4*)b)[lane];
    float hx = fmaxf(ax * nd + bv.x, 0.f);
    float hy = fmaxf(ay * nd + bv.y, 0.f);
    float hz = fmaxf(az * nd + bv.z, 0.f);
    float hw = fmaxf(aw * nd + bv.w, 0.f);

    if (!FUSE_POOL) {
        ((float4*)hout)[n * 32 + lane] = make_float4(hx, hy, hz, hw);
    } else {
        float4 wd = ((const float4*)Wd)[lane];
        float z = hx * wd.x + hy * wd.y + hz * wd.z + hw * wd.w;
        #pragma unroll
        for (int off = 16; off > 0; off >>= 1)
            z += __shfl_xor_sync(0xffffffffu, z, off);
        if (lane == 0) atomicAdd(&g_gsum[gids[n]], z);
    }
}

__global__ void k_final(const float* __restrict__ bd, float* __restrict__ out) {
    int g = threadIdx.x;
    if (g < N_GRAPHS)
        out[g] = g_gsum[g] / fmaxf((float)g_gcnt[g], 1.f) + bd[0];
}

// ---------------- launch ----------------
extern "C" void kernel_launch(void* const* d_in, const int* in_sizes, int n_in,
                              void* d_out, int out_size) {
    const float* in_feat = (const float*)d_in[0];
    const int*   src     = (const int*)  d_in[1];
    const int*   dst     = (const int*)  d_in[2];
    const int*   gids    = (const int*)  d_in[3];
    const float* W1      = (const float*)d_in[4];
    const float* b1      = (const float*)d_in[5];
    const float* W2      = (const float*)d_in[6];
    const float* b2      = (const float*)d_in[7];
    const float* Wd      = (const float*)d_in[8];
    const float* bd      = (const float*)d_in[9];
    float* out = (float*)d_out;

    const int TB = 256;
    int nodeBlocks  = (N_NODES + TB - 1) / TB;
    int edgeBlocks  = (N_EDGES + TB - 1) / TB;
    int layerBlocks = (N_NODES + 8 - 1) / 8;

    float* y  = g_y;
    float* h1 = g_h1;

    k_init      <<<nodeBlocks, TB>>>();                    // 0
    k_degree    <<<edgeBlocks, TB>>>(src, dst);            // 1
    k_norms_scan<<<1, 256>>>(gids);                        // 2
    k_scatter   <<<edgeBlocks, TB>>>(src, dst);            // 3
    k_gemm      <<<layerBlocks, TB>>>(in_feat, W1, y);     // 4
    k_agg<false><<<layerBlocks, TB>>>(y, b1, h1, nullptr, nullptr); // 5 (ncu target)
    k_gemm      <<<layerBlocks, TB>>>(h1, W2, y);          // 6
    k_agg<true> <<<layerBlocks, TB>>>(y, b2, nullptr, Wd, gids);    // 7
    k_final     <<<1, 64>>>(bd, out);                      // 8
}

// round 6
// speedup vs baseline: 1.9856x; 1.9856x over previous
#include <cuda_runtime.h>

#define N_NODES  10000
#define N_EDGES  640000
#define N_GRAPHS 64
#define F        128          // feature dim (in = hidden = 128)

// ---------------- scratch (no allocations allowed) ----------------
__device__ int   g_deg_out[N_NODES];
__device__ int   g_deg_in [N_NODES];
__device__ float g_norm_src[N_NODES];
__device__ float g_norm_dst[N_NODES];
__device__ int   g_row_ptr[N_NODES + 1];
__device__ int   g_cursor [N_NODES];
__device__ int   g_csr    [N_EDGES];       // src ids grouped by dst
__device__ float g_h1     [N_NODES * F];   // layer-1 output
__device__ float g_gsum   [N_GRAPHS];
__device__ int   g_gcnt   [N_GRAPHS];

// ---------------- init / degrees / norms ----------------
__global__ void k_init() {
    int i = blockIdx.x * blockDim.x + threadIdx.x;
    if (i < N_NODES) { g_deg_out[i] = 0; g_deg_in[i] = 0; }
    if (i < N_GRAPHS) { g_gsum[i] = 0.f; g_gcnt[i] = 0; }
}

__global__ void k_degree(const int* __restrict__ src, const int* __restrict__ dst) {
    int e = blockIdx.x * blockDim.x + threadIdx.x;
    if (e < N_EDGES) {
        atomicAdd(&g_deg_out[src[e]], 1);
        atomicAdd(&g_deg_in [dst[e]], 1);
    }
}

__global__ void k_norms(const int* __restrict__ gids) {
    int n = blockIdx.x * blockDim.x + threadIdx.x;
    if (n < N_NODES) {
        g_norm_src[n] = rsqrtf((float)max(g_deg_out[n], 1));
        g_norm_dst[n] = rsqrtf((float)max(g_deg_in [n], 1));
        atomicAdd(&g_gcnt[gids[n]], 1);
    }
}

// ---------------- single-block prefix sum over in-degrees ----------------
__global__ void k_scan() {
    const int T = 256, C = 40;              // 256*40 = 10240 >= N_NODES
    __shared__ int s[T];
    int t = threadIdx.x;
    int base = t * C;
    int local = 0;
    #pragma unroll
    for (int i = 0; i < C; i++) {
        int idx = base + i;
        if (idx < N_NODES) local += g_deg_in[idx];
    }
    s[t] = local;
    __syncthreads();
    for (int off = 1; off < T; off <<= 1) {  // inclusive Hillis-Steele
        int v = (t >= off) ? s[t - off] : 0;
        __syncthreads();
        s[t] += v;
        __syncthreads();
    }
    int run = (t == 0) ? 0 : s[t - 1];       // exclusive prefix of my chunk
    for (int i = 0; i < C; i++) {
        int idx = base + i;
        if (idx < N_NODES) {
            g_row_ptr[idx] = run;
            g_cursor [idx] = run;
            run += g_deg_in[idx];
        }
    }
    if (t == T - 1) g_row_ptr[N_NODES] = run; // = total edges
}

__global__ void k_scatter(const int* __restrict__ src, const int* __restrict__ dst) {
    int e = blockIdx.x * blockDim.x + threadIdx.x;
    if (e < N_EDGES) {
        int pos = atomicAdd(&g_cursor[dst[e]], 1);
        g_csr[pos] = src[e];
    }
}

// ---------------- fused layer: gather (CSR) + GEMM + bias + relu ----------------
// warp-per-node. Lane l owns output columns [4l, 4l+4).
// FUSE_POOL: instead of storing h, compute z = h . Wd, warp-reduce, atomicAdd to graph sum.
template <bool FUSE_POOL>
__global__ void k_layer(const float* __restrict__ x,
                        const float* __restrict__ W,
                        const float* __restrict__ b,
                        float* __restrict__ hout,
                        const float* __restrict__ Wd,
                        const int*  __restrict__ gids) {
    const int WARPS = 8;
    __shared__ float rowbuf[WARPS][F];
    int w    = threadIdx.x >> 5;
    int lane = threadIdx.x & 31;
    int n    = blockIdx.x * WARPS + w;
    if (n >= N_NODES) return;

    int beg = g_row_ptr[n], end = g_row_ptr[n + 1];
    const float4* X4 = (const float4*)x;

    float ax = 0.f, ay = 0.f, az = 0.f, aw = 0.f;
    int e = beg;
    // 8-way unroll: 16 independent loads in flight (8 idx + 8 rows)
    for (; e + 8 <= end; e += 8) {
        int s0 = g_csr[e+0], s1 = g_csr[e+1], s2 = g_csr[e+2], s3 = g_csr[e+3];
        int s4 = g_csr[e+4], s5 = g_csr[e+5], s6 = g_csr[e+6], s7 = g_csr[e+7];
        float w0 = g_norm_src[s0], w1 = g_norm_src[s1],
              w2 = g_norm_src[s2], w3 = g_norm_src[s3];
        float w4 = g_norm_src[s4], w5 = g_norm_src[s5],
              w6 = g_norm_src[s6], w7 = g_norm_src[s7];
        float4 x0 = X4[s0 * 32 + lane];
        float4 x1 = X4[s1 * 32 + lane];
        float4 x2 = X4[s2 * 32 + lane];
        float4 x3 = X4[s3 * 32 + lane];
        float4 x4 = X4[s4 * 32 + lane];
        float4 x5 = X4[s5 * 32 + lane];
        float4 x6 = X4[s6 * 32 + lane];
        float4 x7 = X4[s7 * 32 + lane];
        ax += (w0 * x0.x + w1 * x1.x) + (w2 * x2.x + w3 * x3.x)
            + (w4 * x4.x + w5 * x5.x) + (w6 * x6.x + w7 * x7.x);
        ay += (w0 * x0.y + w1 * x1.y) + (w2 * x2.y + w3 * x3.y)
            + (w4 * x4.y + w5 * x5.y) + (w6 * x6.y + w7 * x7.y);
        az += (w0 * x0.z + w1 * x1.z) + (w2 * x2.z + w3 * x3.z)
            + (w4 * x4.z + w5 * x5.z) + (w6 * x6.z + w7 * x7.z);
        aw += (w0 * x0.w + w1 * x1.w) + (w2 * x2.w + w3 * x3.w)
            + (w4 * x4.w + w5 * x5.w) + (w6 * x6.w + w7 * x7.w);
    }
    for (; e < end; e++) {
        int s = g_csr[e];
        float ws = g_norm_src[s];
        float4 xv = X4[s * 32 + lane];
        ax += ws * xv.x; ay += ws * xv.y; az += ws * xv.z; aw += ws * xv.w;
    }

    float nd = g_norm_dst[n];
    rowbuf[w][lane * 4 + 0] = ax * nd;
    rowbuf[w][lane * 4 + 1] = ay * nd;
    rowbuf[w][lane * 4 + 2] = az * nd;
    rowbuf[w][lane * 4 + 3] = aw * nd;
    __syncwarp();

    // GEMM: o[c] = sum_k row[k] * W[k][c] + b[c]
    const float4* W4 = (const float4*)W;
    float4 bv = ((const float4*)b)[lane];
    float ox = bv.x, oy = bv.y, oz = bv.z, ow = bv.w;
    #pragma unroll 16
    for (int k = 0; k < F; k++) {
        float av  = rowbuf[w][k];              // LDS broadcast
        float4 wv = W4[k * 32 + lane];         // L1-resident after warmup
        ox += av * wv.x; oy += av * wv.y; oz += av * wv.z; ow += av * wv.w;
    }
    ox = fmaxf(ox, 0.f); oy = fmaxf(oy, 0.f);
    oz = fmaxf(oz, 0.f); ow = fmaxf(ow, 0.f);

    if (!FUSE_POOL) {
        ((float4*)hout)[n * 32 + lane] = make_float4(ox, oy, oz, ow);
    } else {
        float4 wd = ((const float4*)Wd)[lane];
        float z = ox * wd.x + oy * wd.y + oz * wd.z + ow * wd.w;
        #pragma unroll
        for (int off = 16; off > 0; off >>= 1)
            z += __shfl_xor_sync(0xffffffffu, z, off);
        if (lane == 0) atomicAdd(&g_gsum[gids[n]], z);
    }
}

__global__ void k_final(const float* __restrict__ bd, float* __restrict__ out) {
    int g = threadIdx.x;
    if (g < N_GRAPHS)
        out[g] = g_gsum[g] / fmaxf((float)g_gcnt[g], 1.f) + bd[0];
}

// ---------------- launch ----------------
extern "C" void kernel_launch(void* const* d_in, const int* in_sizes, int n_in,
                              void* d_out, int out_size) {
    const float* in_feat = (const float*)d_in[0];
    const int*   src     = (const int*)  d_in[1];
    const int*   dst     = (const int*)  d_in[2];
    const int*   gids    = (const int*)  d_in[3];
    const float* W1      = (const float*)d_in[4];
    const float* b1      = (const float*)d_in[5];
    const float* W2      = (const float*)d_in[6];
    const float* b2      = (const float*)d_in[7];
    const float* Wd      = (const float*)d_in[8];
    const float* bd      = (const float*)d_in[9];
    float* out = (float*)d_out;

    const int TB = 256;
    int nodeBlocks = (N_NODES + TB - 1) / TB;
    int edgeBlocks = (N_EDGES + TB - 1) / TB;
    int layerBlocks = (N_NODES + 8 - 1) / 8;   // warp-per-node, 8 warps/block

    k_init<<<nodeBlocks, TB>>>();
    k_degree<<<edgeBlocks, TB>>>(src, dst);
    k_norms<<<nodeBlocks, TB>>>(gids);
    k_scan<<<1, 256>>>();
    k_scatter<<<edgeBlocks, TB>>>(src, dst);
    k_layer<false><<<layerBlocks, TB>>>(in_feat, W1, b1, g_h1, nullptr, nullptr);
    k_layer<true ><<<layerBlocks, TB>>>(g_h1,    W2, b2, nullptr, Wd, gids);
    k_final<<<1, 64>>>(bd, out);
}

// round 7
// speedup vs baseline: 21.7489x; 10.9536x over previous
#include <cuda_runtime.h>

#define N_NODES  10000
#define N_EDGES  640000
#define N_GRAPHS 64
#define F        128          // feature dim (in = hidden = 128)

// ---------------- scratch (device symbols; NEVER passed as kernel args) ----------------
__device__ int   g_deg_out[N_NODES];
__device__ int   g_deg_in [N_NODES];
__device__ float g_norm_src[N_NODES];
__device__ float g_norm_dst[N_NODES];
__device__ int   g_row_ptr[N_NODES + 1];
__device__ int   g_cursor [N_NODES];
__device__ int   g_csr    [N_EDGES];       // src ids grouped by dst
__device__ float g_h1     [N_NODES * F];   // layer-1 output (accessed by symbol only!)
__device__ float g_gsum   [N_GRAPHS];
__device__ int   g_gcnt   [N_GRAPHS];

// ---------------- init / degrees / norms ----------------
__global__ void k_init() {
    int i = blockIdx.x * blockDim.x + threadIdx.x;
    if (i < N_NODES) { g_deg_out[i] = 0; g_deg_in[i] = 0; }
    if (i < N_GRAPHS) { g_gsum[i] = 0.f; g_gcnt[i] = 0; }
}

__global__ void k_degree(const int* __restrict__ src, const int* __restrict__ dst) {
    int e = blockIdx.x * blockDim.x + threadIdx.x;
    if (e < N_EDGES) {
        atomicAdd(&g_deg_out[src[e]], 1);
        atomicAdd(&g_deg_in [dst[e]], 1);
    }
}

__global__ void k_norms(const int* __restrict__ gids) {
    int n = blockIdx.x * blockDim.x + threadIdx.x;
    if (n < N_NODES) {
        g_norm_src[n] = rsqrtf((float)max(g_deg_out[n], 1));
        g_norm_dst[n] = rsqrtf((float)max(g_deg_in [n], 1));
        atomicAdd(&g_gcnt[gids[n]], 1);
    }
}

// ---------------- single-block prefix sum over in-degrees ----------------
__global__ void k_scan() {
    const int T = 256, C = 40;              // 256*40 = 10240 >= N_NODES
    __shared__ int s[T];
    int t = threadIdx.x;
    int base = t * C;
    int local = 0;
    #pragma unroll
    for (int i = 0; i < C; i++) {
        int idx = base + i;
        if (idx < N_NODES) local += g_deg_in[idx];
    }
    s[t] = local;
    __syncthreads();
    for (int off = 1; off < T; off <<= 1) {  // inclusive Hillis-Steele
        int v = (t >= off) ? s[t - off] : 0;
        __syncthreads();
        s[t] += v;
        __syncthreads();
    }
    int run = (t == 0) ? 0 : s[t - 1];       // exclusive prefix of my chunk
    for (int i = 0; i < C; i++) {
        int idx = base + i;
        if (idx < N_NODES) {
            g_row_ptr[idx] = run;
            g_cursor [idx] = run;
            run += g_deg_in[idx];
        }
    }
    if (t == T - 1) g_row_ptr[N_NODES] = run; // = total edges
}

__global__ void k_scatter(const int* __restrict__ src, const int* __restrict__ dst) {
    int e = blockIdx.x * blockDim.x + threadIdx.x;
    if (e < N_EDGES) {
        int pos = atomicAdd(&g_cursor[dst[e]], 1);
        g_csr[pos] = src[e];
    }
}

// ---------------- fused layer: gather (CSR) + GEMM + bias + relu ----------------
// warp-per-node. Lane l owns output columns [4l, 4l+4).
// Layer 1 (FUSE_POOL=false): x = x_arg (in_feat), writes g_h1 BY SYMBOL.
// Layer 2 (FUSE_POOL=true):  x = g_h1 BY SYMBOL, pools into g_gsum.
template <bool FUSE_POOL>
__global__ void k_layer(const float* __restrict__ x_arg,
                        const float* __restrict__ W,
                        const float* __restrict__ b,
                        const float* __restrict__ Wd,
                        const int*  __restrict__ gids) {
    const int WARPS = 8;
    __shared__ float rowbuf[WARPS][F];
    int w    = threadIdx.x >> 5;
    int lane = threadIdx.x & 31;
    int n    = blockIdx.x * WARPS + w;
    if (n >= N_NODES) return;

    const float* x = FUSE_POOL ? (const float*)g_h1 : x_arg;  // symbol, not arg

    int beg = g_row_ptr[n], end = g_row_ptr[n + 1];
    const float4* X4 = (const float4*)x;

    float ax = 0.f, ay = 0.f, az = 0.f, aw = 0.f;
    int e = beg;
    for (; e + 8 <= end; e += 8) {
        int s0 = g_csr[e+0], s1 = g_csr[e+1], s2 = g_csr[e+2], s3 = g_csr[e+3];
        int s4 = g_csr[e+4], s5 = g_csr[e+5], s6 = g_csr[e+6], s7 = g_csr[e+7];
        float w0 = g_norm_src[s0], w1 = g_norm_src[s1],
              w2 = g_norm_src[s2], w3 = g_norm_src[s3];
        float w4 = g_norm_src[s4], w5 = g_norm_src[s5],
              w6 = g_norm_src[s6], w7 = g_norm_src[s7];
        float4 x0 = X4[s0 * 32 + lane];
        float4 x1 = X4[s1 * 32 + lane];
        float4 x2 = X4[s2 * 32 + lane];
        float4 x3 = X4[s3 * 32 + lane];
        float4 x4 = X4[s4 * 32 + lane];
        float4 x5 = X4[s5 * 32 + lane];
        float4 x6 = X4[s6 * 32 + lane];
        float4 x7 = X4[s7 * 32 + lane];
        ax += (w0 * x0.x + w1 * x1.x) + (w2 * x2.x + w3 * x3.x)
            + (w4 * x4.x + w5 * x5.x) + (w6 * x6.x + w7 * x7.x);
        ay += (w0 * x0.y + w1 * x1.y) + (w2 * x2.y + w3 * x3.y)
            + (w4 * x4.y + w5 * x5.y) + (w6 * x6.y + w7 * x7.y);
        az += (w0 * x0.z + w1 * x1.z) + (w2 * x2.z + w3 * x3.z)
            + (w4 * x4.z + w5 * x5.z) + (w6 * x6.z + w7 * x7.z);
        aw += (w0 * x0.w + w1 * x1.w) + (w2 * x2.w + w3 * x3.w)
            + (w4 * x4.w + w5 * x5.w) + (w6 * x6.w + w7 * x7.w);
    }
    for (; e < end; e++) {
        int s = g_csr[e];
        float ws = g_norm_src[s];
        float4 xv = X4[s * 32 + lane];
        ax += ws * xv.x; ay += ws * xv.y; az += ws * xv.z; aw += ws * xv.w;
    }

    float nd = g_norm_dst[n];
    rowbuf[w][lane * 4 + 0] = ax * nd;
    rowbuf[w][lane * 4 + 1] = ay * nd;
    rowbuf[w][lane * 4 + 2] = az * nd;
    rowbuf[w][lane * 4 + 3] = aw * nd;
    __syncwarp();

    // GEMM: o[c] = sum_k row[k] * W[k][c] + b[c]
    const float4* W4 = (const float4*)W;
    float4 bv = ((const float4*)b)[lane];
    float ox = bv.x, oy = bv.y, oz = bv.z, ow = bv.w;
    #pragma unroll 16
    for (int k = 0; k < F; k++) {
        float av  = rowbuf[w][k];              // LDS broadcast
        float4 wv = W4[k * 32 + lane];         // L1-resident after warmup
        ox += av * wv.x; oy += av * wv.y; oz += av * wv.z; ow += av * wv.w;
    }
    ox = fmaxf(ox, 0.f); oy = fmaxf(oy, 0.f);
    oz = fmaxf(oz, 0.f); ow = fmaxf(ow, 0.f);

    if (!FUSE_POOL) {
        ((float4*)g_h1)[n * 32 + lane] = make_float4(ox, oy, oz, ow);  // symbol
    } else {
        float4 wd = ((const float4*)Wd)[lane];
        float z = ox * wd.x + oy * wd.y + oz * wd.z + ow * wd.w;
        #pragma unroll
        for (int off = 16; off > 0; off >>= 1)
            z += __shfl_xor_sync(0xffffffffu, z, off);
        if (lane == 0) atomicAdd(&g_gsum[gids[n]], z);
    }
}

__global__ void k_final(const float* __restrict__ bd, float* __restrict__ out) {
    int g = threadIdx.x;
    if (g < N_GRAPHS)
        out[g] = g_gsum[g] / fmaxf((float)g_gcnt[g], 1.f) + bd[0];
}

// ---------------- launch ----------------
extern "C" void kernel_launch(void* const* d_in, const int* in_sizes, int n_in,
                              void* d_out, int out_size) {
    const float* in_feat = (const float*)d_in[0];
    const int*   src     = (const int*)  d_in[1];
    const int*   dst     = (const int*)  d_in[2];
    const int*   gids    = (const int*)  d_in[3];
    const float* W1      = (const float*)d_in[4];
    const float* b1      = (const float*)d_in[5];
    const float* W2      = (const float*)d_in[6];
    const float* b2      = (const float*)d_in[7];
    const float* Wd      = (const float*)d_in[8];
    const float* bd      = (const float*)d_in[9];
    float* out = (float*)d_out;

    const int TB = 256;
    int nodeBlocks = (N_NODES + TB - 1) / TB;
    int edgeBlocks = (N_EDGES + TB - 1) / TB;
    int layerBlocks = (N_NODES + 8 - 1) / 8;   // warp-per-node, 8 warps/block

    k_init<<<nodeBlocks, TB>>>();
    k_degree<<<edgeBlocks, TB>>>(src, dst);
    k_norms<<<nodeBlocks, TB>>>(gids);
    k_scan<<<1, 256>>>();
    k_scatter<<<edgeBlocks, TB>>>(src, dst);
    k_layer<false><<<layerBlocks, TB>>>(in_feat, W1, b1, nullptr, nullptr);
    k_layer<true ><<<layerBlocks, TB>>>(nullptr, W2, b2, Wd, gids);
    k_final<<<1, 64>>>(bd, out);
}

// round 8
// speedup vs baseline: 25.6504x; 1.1794x over previous
#include <cuda_runtime.h>
#include <cuda_fp16.h>

#define N_NODES  10000
#define N_EDGES  640000
#define N_GRAPHS 64
#define F        128

// -------- device symbols: ONLY dereferenced inside kernels, never passed as args --------
__device__ int    g_deg_out[N_NODES];          // zeroed at load + by k_final each run
__device__ int    g_deg_in [N_NODES];
__device__ float  g_norm_src[N_NODES];
__device__ float  g_norm_dst[N_NODES];
__device__ int    g_row_ptr[N_NODES + 1];
__device__ int    g_cursor [N_NODES];
__device__ int    g_csr    [N_EDGES];
__device__ __half g_xh     [N_NODES * F];      // in_feat * norm_src   (fp16)
__device__ __half g_h1h    [N_NODES * F];      // relu(layer1) * norm_src (fp16)
__device__ float  g_gsum   [N_GRAPHS];
__device__ float  g_ginv   [N_GRAPHS];

// ---------------- [0] degrees (arrays arrive zeroed; re-zeroed by k_final) ----------------
__global__ void k_degree(const int* __restrict__ src, const int* __restrict__ dst) {
    int e = blockIdx.x * blockDim.x + threadIdx.x;
    if (e < N_EDGES) {
        atomicAdd(&g_deg_out[src[e]], 1);
        atomicAdd(&g_deg_in [dst[e]], 1);
    }
}

// ---------------- [1] prep: norms + graph counts + scan + cursors (1 block, 1024 thr) -------
__global__ void k_prep(const int* __restrict__ gids) {
    const int T = 1024, C = 10;                // 1024*10 = 10240 >= N_NODES
    __shared__ int s[T];
    __shared__ int cnt[N_GRAPHS];
    int t = threadIdx.x;
    if (t < N_GRAPHS) cnt[t] = 0;
    __syncthreads();

    for (int n = t; n < N_NODES; n += T) {
        g_norm_src[n] = rsqrtf((float)max(g_deg_out[n], 1));
        g_norm_dst[n] = rsqrtf((float)max(g_deg_in [n], 1));
        atomicAdd(&cnt[gids[n]], 1);
    }

    int base = t * C;
    int local = 0;
    #pragma unroll
    for (int i = 0; i < C; i++) {
        int idx = base + i;
        if (idx < N_NODES) local += g_deg_in[idx];
    }
    s[t] = local;
    __syncthreads();
    for (int off = 1; off < T; off <<= 1) {    // inclusive Hillis-Steele
        int v = (t >= off) ? s[t - off] : 0;
        __syncthreads();
        s[t] += v;
        __syncthreads();
    }
    int run = (t == 0) ? 0 : s[t - 1];
    #pragma unroll
    for (int i = 0; i < C; i++) {
        int idx = base + i;
        if (idx < N_NODES) {
            g_row_ptr[idx] = run;
            g_cursor [idx] = run;
            run += g_deg_in[idx];
        }
    }
    if (t == T - 1) g_row_ptr[N_NODES] = run;

    if (t < N_GRAPHS) {
        g_gsum[t] = 0.f;
        g_ginv[t] = 1.f / fmaxf((float)cnt[t], 1.f);
    }
}

// ---------------- [2] scatter edges into CSR + prescale X to fp16 (one grid) --------------
#define TB 256
#define EDGE_BLOCKS ((N_EDGES + TB - 1) / TB)
#define XS_BLOCKS   ((N_NODES * (F / 4) + TB - 1) / TB)

__global__ void k_scatter_scale(const int* __restrict__ src,
                                const int* __restrict__ dst,
                                const float* __restrict__ X) {
    int b = blockIdx.x;
    if (b < EDGE_BLOCKS) {
        int e = b * TB + threadIdx.x;
        if (e < N_EDGES) {
            int pos = atomicAdd(&g_cursor[dst[e]], 1);
            g_csr[pos] = src[e];
        }
    } else {
        int idx = (b - EDGE_BLOCKS) * TB + threadIdx.x;   // one float4 -> one uint2
        if (idx < N_NODES * (F / 4)) {
            float s = g_norm_src[idx >> 5];                // 32 slots per node
            float4 v = ((const float4*)X)[idx];
            __half2 h0 = __floats2half2_rn(v.x * s, v.y * s);
            __half2 h1 = __floats2half2_rn(v.z * s, v.w * s);
            uint2 o;
            o.x = *(unsigned*)&h0;
            o.y = *(unsigned*)&h1;
            ((uint2*)g_xh)[idx] = o;
        }
    }
}

// ---------------- [3]/[4] fused layer: fp16 gather (CSR) + fp32 GEMM + relu ----------------
// warp-per-node, 8 warps/block. Lane owns 4 features / 4 output columns.
template <int LAYER>    // 1: read g_xh, write g_h1h; 2: read g_h1h, fused pool
__global__ __launch_bounds__(256) void k_layer(const float* __restrict__ W,
                                               const float* __restrict__ b,
                                               const float* __restrict__ Wd,
                                               const int*  __restrict__ gids) {
    const int WARPS = 8;
    __shared__ float rowbuf[WARPS][F];
    int w    = threadIdx.x >> 5;
    int lane = threadIdx.x & 31;
    int n    = blockIdx.x * WARPS + w;
    if (n >= N_NODES) return;

    const uint2* X = (const uint2*)(LAYER == 1 ? (const __half*)g_xh
                                               : (const __half*)g_h1h);

    int beg = g_row_ptr[n], end = g_row_ptr[n + 1];
    float ax = 0.f, ay = 0.f, az = 0.f, aw = 0.f;
    int e = beg;
    for (; e + 8 <= end; e += 8) {                 // 16 loads in flight
        int s0 = g_csr[e+0], s1 = g_csr[e+1], s2 = g_csr[e+2], s3 = g_csr[e+3];
        int s4 = g_csr[e+4], s5 = g_csr[e+5], s6 = g_csr[e+6], s7 = g_csr[e+7];
        uint2 v0 = X[s0 * 32 + lane];
        uint2 v1 = X[s1 * 32 + lane];
        uint2 v2 = X[s2 * 32 + lane];
        uint2 v3 = X[s3 * 32 + lane];
        uint2 v4 = X[s4 * 32 + lane];
        uint2 v5 = X[s5 * 32 + lane];
        uint2 v6 = X[s6 * 32 + lane];
        uint2 v7 = X[s7 * 32 + lane];
        #define ACC(v) { \
            float2 f0 = __half22float2(*(__half2*)&(v).x); \
            float2 f1 = __half22float2(*(__half2*)&(v).y); \
            ax += f0.x; ay += f0.y; az += f1.x; aw += f1.y; }
        ACC(v0) ACC(v1) ACC(v2) ACC(v3) ACC(v4) ACC(v5) ACC(v6) ACC(v7)
    }
    for (; e < end; e++) {
        int s = g_csr[e];
        uint2 v = X[s * 32 + lane];
        ACC(v)
        #undef ACC
    }

    float nd = g_norm_dst[n];
    rowbuf[w][lane * 4 + 0] = ax * nd;
    rowbuf[w][lane * 4 + 1] = ay * nd;
    rowbuf[w][lane * 4 + 2] = az * nd;
    rowbuf[w][lane * 4 + 3] = aw * nd;
    __syncwarp();

    // GEMM (fp32): o[c] = sum_k row[k] * W[k][c] + b[c]
    const float4* W4 = (const float4*)W;
    float4 bv = ((const float4*)b)[lane];
    float ox = bv.x, oy = bv.y, oz = bv.z, ow = bv.w;
    #pragma unroll 16
    for (int k = 0; k < F; k++) {
        float av  = rowbuf[w][k];
        float4 wv = W4[k * 32 + lane];
        ox += av * wv.x; oy += av * wv.y; oz += av * wv.z; ow += av * wv.w;
    }
    ox = fmaxf(ox, 0.f); oy = fmaxf(oy, 0.f);
    oz = fmaxf(oz, 0.f); ow = fmaxf(ow, 0.f);

    if (LAYER == 1) {
        float ns = g_norm_src[n];                  // prescale for layer-2 gather
        __half2 h0 = __floats2half2_rn(ox * ns, oy * ns);
        __half2 h1 = __floats2half2_rn(oz * ns, ow * ns);
        uint2 o;
        o.x = *(unsigned*)&h0;
        o.y = *(unsigned*)&h1;
        ((uint2*)g_h1h)[n * 32 + lane] = o;
    } else {
        float4 wd = ((const float4*)Wd)[lane];
        float z = ox * wd.x + oy * wd.y + oz * wd.z + ow * wd.w;
        #pragma unroll
        for (int off = 16; off > 0; off >>= 1)
            z += __shfl_xor_sync(0xffffffffu, z, off);
        if (lane == 0) atomicAdd(&g_gsum[gids[n]], z);
    }
}

// ---------------- [5] readout + re-zero degree arrays for next run ----------------
__global__ void k_final(const float* __restrict__ bd, float* __restrict__ out) {
    int i = blockIdx.x * blockDim.x + threadIdx.x;
    if (i < N_NODES) { g_deg_out[i] = 0; g_deg_in[i] = 0; }
    if (i < N_GRAPHS) out[i] = g_gsum[i] * g_ginv[i] + bd[0];
}

// ---------------- launch ----------------
extern "C" void kernel_launch(void* const* d_in, const int* in_sizes, int n_in,
                              void* d_out, int out_size) {
    const float* in_feat = (const float*)d_in[0];
    const int*   src     = (const int*)  d_in[1];
    const int*   dst     = (const int*)  d_in[2];
    const int*   gids    = (const int*)  d_in[3];
    const float* W1      = (const float*)d_in[4];
    const float* b1      = (const float*)d_in[5];
    const float* W2      = (const float*)d_in[6];
    const float* b2      = (const float*)d_in[7];
    const float* Wd      = (const float*)d_in[8];
    const float* bd      = (const float*)d_in[9];
    float* out = (float*)d_out;

    int layerBlocks = (N_NODES + 7) / 8;
    int finalBlocks = (N_NODES + TB - 1) / TB;

    k_degree        <<<EDGE_BLOCKS, TB>>>(src, dst);                 // 0
    k_prep          <<<1, 1024>>>(gids);                             // 1
    k_scatter_scale <<<EDGE_BLOCKS + XS_BLOCKS, TB>>>(src, dst, in_feat); // 2
    k_layer<1>      <<<layerBlocks, TB>>>(W1, b1, nullptr, nullptr); // 3  (ncu slot)
    k_layer<2>      <<<layerBlocks, TB>>>(W2, b2, Wd, gids);         // 4
    k_final         <<<finalBlocks, TB>>>(bd, out);                  // 5
}

// round 9
// speedup vs baseline: 27.3009x; 1.0643x over previous
#include <cuda_runtime.h>
#include <cuda_fp16.h>

#define N_NODES  10000
#define N_EDGES  640000
#define N_GRAPHS 64
#define F        128

// -------- device symbols: ONLY dereferenced inside kernels, never passed as args --------
__device__ int    g_deg_out[N_NODES];          // zeroed at load + by k_final each run
__device__ int    g_deg_in [N_NODES];
__device__ float  g_norm_src[N_NODES];
__device__ float  g_norm_dst[N_NODES];
__device__ int    g_row_ptr[N_NODES + 1];
__device__ int    g_cursor [N_NODES];
__device__ int    g_csr    [N_EDGES];
__device__ __half g_xh     [N_NODES * F];      // in_feat * norm_src   (fp16)
__device__ __half g_h1h    [N_NODES * F];      // relu(layer1) * norm_src (fp16)
__device__ float  g_gsum   [N_GRAPHS];
__device__ float  g_ginv   [N_GRAPHS];

// ---------------- [0] degrees ----------------
__global__ void k_degree(const int* __restrict__ src, const int* __restrict__ dst) {
    int e = blockIdx.x * blockDim.x + threadIdx.x;
    if (e < N_EDGES) {
        atomicAdd(&g_deg_out[src[e]], 1);
        atomicAdd(&g_deg_in [dst[e]], 1);
    }
}

// ---------------- [1] prep: norms + graph counts + scan + cursors (1 block) ----------------
__global__ void k_prep(const int* __restrict__ gids) {
    const int T = 1024, C = 10;                // 1024*10 = 10240 >= N_NODES
    __shared__ int s[T];
    __shared__ int cnt[N_GRAPHS];
    int t = threadIdx.x;
    if (t < N_GRAPHS) cnt[t] = 0;
    __syncthreads();

    for (int n = t; n < N_NODES; n += T) {
        g_norm_src[n] = rsqrtf((float)max(g_deg_out[n], 1));
        g_norm_dst[n] = rsqrtf((float)max(g_deg_in [n], 1));
        atomicAdd(&cnt[gids[n]], 1);
    }

    int base = t * C;
    int local = 0;
    #pragma unroll
    for (int i = 0; i < C; i++) {
        int idx = base + i;
        if (idx < N_NODES) local += g_deg_in[idx];
    }
    s[t] = local;
    __syncthreads();
    for (int off = 1; off < T; off <<= 1) {
        int v = (t >= off) ? s[t - off] : 0;
        __syncthreads();
        s[t] += v;
        __syncthreads();
    }
    int run = (t == 0) ? 0 : s[t - 1];
    #pragma unroll
    for (int i = 0; i < C; i++) {
        int idx = base + i;
        if (idx < N_NODES) {
            g_row_ptr[idx] = run;
            g_cursor [idx] = run;
            run += g_deg_in[idx];
        }
    }
    if (t == T - 1) g_row_ptr[N_NODES] = run;

    if (t < N_GRAPHS) {
        g_gsum[t] = 0.f;
        g_ginv[t] = 1.f / fmaxf((float)cnt[t], 1.f);
    }
}

// ---------------- [2] scatter edges into CSR + prescale X to fp16 (one grid) --------------
#define TB 256
#define EDGE_BLOCKS ((N_EDGES + TB - 1) / TB)
#define XS_BLOCKS   ((N_NODES * (F / 4) + TB - 1) / TB)

__global__ void k_scatter_scale(const int* __restrict__ src,
                                const int* __restrict__ dst,
                                const float* __restrict__ X) {
    int b = blockIdx.x;
    if (b < EDGE_BLOCKS) {
        int e = b * TB + threadIdx.x;
        if (e < N_EDGES) {
            int pos = atomicAdd(&g_cursor[dst[e]], 1);
            g_csr[pos] = src[e];
        }
    } else {
        int idx = (b - EDGE_BLOCKS) * TB + threadIdx.x;
        if (idx < N_NODES * (F / 4)) {
            float s = g_norm_src[idx >> 5];
            float4 v = ((const float4*)X)[idx];
            __half2 h0 = __floats2half2_rn(v.x * s, v.y * s);
            __half2 h1 = __floats2half2_rn(v.z * s, v.w * s);
            uint2 o;
            o.x = *(unsigned*)&h0;
            o.y = *(unsigned*)&h1;
            ((uint2*)g_xh)[idx] = o;
        }
    }
}

// ---------------- [3]/[4] fused layer: fp16 gather + fp32 GEMM (W amortized x4) -----------
// 8 warps/block, each warp owns 4 nodes. Lane owns 4 output columns.
#define NPW   4                         // nodes per warp
#define WARPS 8
#define NPB   (NPW * WARPS)             // 32 nodes per block

template <int LAYER>    // 1: read g_xh, write g_h1h; 2: read g_h1h, fused pool
__global__ __launch_bounds__(256) void k_layer(const float* __restrict__ W,
                                               const float* __restrict__ b,
                                               const float* __restrict__ Wd,
                                               const int*  __restrict__ gids) {
    __shared__ float rowbuf[NPB][F];
    int w    = threadIdx.x >> 5;
    int lane = threadIdx.x & 31;
    int n0   = blockIdx.x * NPB + w * NPW;

    const uint2* X = (const uint2*)(LAYER == 1 ? (const __half*)g_xh
                                               : (const __half*)g_h1h);

    // ---- gather 4 nodes (sequential per warp, 8-deep MLP each) ----
    #pragma unroll
    for (int j = 0; j < NPW; j++) {
        int n = n0 + j;
        if (n >= N_NODES) break;
        int beg = g_row_ptr[n], end = g_row_ptr[n + 1];
        float ax = 0.f, ay = 0.f, az = 0.f, aw = 0.f;
        int e = beg;
        #define ACC(v) { \
            float2 f0 = __half22float2(*(__half2*)&(v).x); \
            float2 f1 = __half22float2(*(__half2*)&(v).y); \
            ax += f0.x; ay += f0.y; az += f1.x; aw += f1.y; }
        for (; e + 8 <= end; e += 8) {
            int s0 = g_csr[e+0], s1 = g_csr[e+1], s2 = g_csr[e+2], s3 = g_csr[e+3];
            int s4 = g_csr[e+4], s5 = g_csr[e+5], s6 = g_csr[e+6], s7 = g_csr[e+7];
            uint2 v0 = X[s0 * 32 + lane];
            uint2 v1 = X[s1 * 32 + lane];
            uint2 v2 = X[s2 * 32 + lane];
            uint2 v3 = X[s3 * 32 + lane];
            uint2 v4 = X[s4 * 32 + lane];
            uint2 v5 = X[s5 * 32 + lane];
            uint2 v6 = X[s6 * 32 + lane];
            uint2 v7 = X[s7 * 32 + lane];
            ACC(v0) ACC(v1) ACC(v2) ACC(v3) ACC(v4) ACC(v5) ACC(v6) ACC(v7)
        }
        for (; e < end; e++) {
            int s = g_csr[e];
            uint2 v = X[s * 32 + lane];
            ACC(v)
        }
        #undef ACC
        float nd = g_norm_dst[n];
        ((float4*)rowbuf[w * NPW + j])[lane] =           // STS.128 conflict-free
            make_float4(ax * nd, ay * nd, az * nd, aw * nd);
    }
    __syncwarp();

    // ---- GEMM: one W[k] float4 load serves 4 nodes ----
    const float4* W4 = (const float4*)W;
    float4 bv = ((const float4*)b)[lane];
    float o0x = bv.x, o0y = bv.y, o0z = bv.z, o0w = bv.w;
    float o1x = bv.x, o1y = bv.y, o1z = bv.z, o1w = bv.w;
    float o2x = bv.x, o2y = bv.y, o2z = bv.z, o2w = bv.w;
    float o3x = bv.x, o3y = bv.y, o3z = bv.z, o3w = bv.w;
    const float* r0 = rowbuf[w * NPW + 0];
    const float* r1 = rowbuf[w * NPW + 1];
    const float* r2 = rowbuf[w * NPW + 2];
    const float* r3 = rowbuf[w * NPW + 3];
    #pragma unroll 8
    for (int k = 0; k < F; k++) {
        float4 wv = W4[k * 32 + lane];                   // LDG, once per 4 nodes
        float a0 = r0[k], a1 = r1[k], a2 = r2[k], a3 = r3[k];  // LDS broadcasts
        o0x += a0 * wv.x; o0y += a0 * wv.y; o0z += a0 * wv.z; o0w += a0 * wv.w;
        o1x += a1 * wv.x; o1y += a1 * wv.y; o1z += a1 * wv.z; o1w += a1 * wv.w;
        o2x += a2 * wv.x; o2y += a2 * wv.y; o2z += a2 * wv.z; o2w += a2 * wv.w;
        o3x += a3 * wv.x; o3y += a3 * wv.y; o3z += a3 * wv.z; o3w += a3 * wv.w;
    }

    // ---- epilogue per node ----
    #pragma unroll
    for (int j = 0; j < NPW; j++) {
        int n = n0 + j;
        if (n >= N_NODES) break;
        float ox = (j == 0 ? o0x : j == 1 ? o1x : j == 2 ? o2x : o3x);
        float oy = (j == 0 ? o0y : j == 1 ? o1y : j == 2 ? o2y : o3y);
        float oz = (j == 0 ? o0z : j == 1 ? o1z : j == 2 ? o2z : o3z);
        float ow = (j == 0 ? o0w : j == 1 ? o1w : j == 2 ? o2w : o3w);
        ox = fmaxf(ox, 0.f); oy = fmaxf(oy, 0.f);
        oz = fmaxf(oz, 0.f); ow = fmaxf(ow, 0.f);

        if (LAYER == 1) {
            float ns = g_norm_src[n];
            __half2 h0 = __floats2half2_rn(ox * ns, oy * ns);
            __half2 h1 = __floats2half2_rn(oz * ns, ow * ns);
            uint2 o;
            o.x = *(unsigned*)&h0;
            o.y = *(unsigned*)&h1;
            ((uint2*)g_h1h)[n * 32 + lane] = o;
        } else {
            float4 wd = ((const float4*)Wd)[lane];
            float z = ox * wd.x + oy * wd.y + oz * wd.z + ow * wd.w;
            #pragma unroll
            for (int off = 16; off > 0; off >>= 1)
                z += __shfl_xor_sync(0xffffffffu, z, off);
            if (lane == 0) atomicAdd(&g_gsum[gids[n]], z);
        }
    }
}

// ---------------- [5] readout + re-zero degree arrays for next run ----------------
__global__ void k_final(const float* __restrict__ bd, float* __restrict__ out) {
    int i = blockIdx.x * blockDim.x + threadIdx.x;
    if (i < N_NODES) { g_deg_out[i] = 0; g_deg_in[i] = 0; }
    if (i < N_GRAPHS) out[i] = g_gsum[i] * g_ginv[i] + bd[0];
}

// ---------------- launch ----------------
extern "C" void kernel_launch(void* const* d_in, const int* in_sizes, int n_in,
                              void* d_out, int out_size) {
    const float* in_feat = (const float*)d_in[0];
    const int*   src     = (const int*)  d_in[1];
    const int*   dst     = (const int*)  d_in[2];
    const int*   gids    = (const int*)  d_in[3];
    const float* W1      = (const float*)d_in[4];
    const float* b1      = (const float*)d_in[5];
    const float* W2      = (const float*)d_in[6];
    const float* b2      = (const float*)d_in[7];
    const float* Wd      = (const float*)d_in[8];
    const float* bd      = (const float*)d_in[9];
    float* out = (float*)d_out;

    int layerBlocks = (N_NODES + NPB - 1) / NPB;     // 313
    int finalBlocks = (N_NODES + TB - 1) / TB;

    k_degree        <<<EDGE_BLOCKS, TB>>>(src, dst);                 // 0
    k_prep          <<<1, 1024>>>(gids);                             // 1
    k_scatter_scale <<<EDGE_BLOCKS + XS_BLOCKS, TB>>>(src, dst, in_feat); // 2
    k_layer<1>      <<<layerBlocks, TB>>>(W1, b1, nullptr, nullptr); // 3  (ncu slot)
    k_layer<2>      <<<layerBlocks, TB>>>(W2, b2, Wd, gids);         // 4
    k_final         <<<finalBlocks, TB>>>(bd, out);                  // 5
}

// round 10
// speedup vs baseline: 28.7889x; 1.0545x over previous
#include <cuda_runtime.h>
#include <cuda_fp16.h>

#define N_NODES  10000
#define N_EDGES  640000
#define N_GRAPHS 64
#define F        128

// -------- device symbols: ONLY dereferenced inside kernels, never passed as args --------
__device__ int    g_deg_out[N_NODES];          // zeroed at load + by k_final each run
__device__ int    g_deg_in [N_NODES];
__device__ float  g_norm_src[N_NODES];
__device__ float  g_norm_dst[N_NODES];
__device__ int    g_row_ptr[N_NODES + 1];
__device__ int    g_cursor [N_NODES];
__device__ int    g_csr    [N_EDGES];
__device__ __half g_xh     [N_NODES * F];      // in_feat * norm_src   (fp16)
__device__ __half g_h1h    [N_NODES * F];      // relu(layer1) * norm_src (fp16)
__device__ __half g_w1h    [F * F];            // W1 in fp16
__device__ __half g_w2h    [F * F];            // W2 in fp16
__device__ float  g_gsum   [N_GRAPHS];
__device__ float  g_ginv   [N_GRAPHS];

// ---------------- [0] degrees ----------------
__global__ void k_degree(const int* __restrict__ src, const int* __restrict__ dst) {
    int e = blockIdx.x * blockDim.x + threadIdx.x;
    if (e < N_EDGES) {
        atomicAdd(&g_deg_out[src[e]], 1);
        atomicAdd(&g_deg_in [dst[e]], 1);
    }
}

// ---------------- [1] prep: norms + graph counts + shuffle-scan + cursors (1 block) --------
__global__ void k_prep(const int* __restrict__ gids) {
    const int T = 1024, C = 10;                // 1024*10 = 10240 >= N_NODES
    __shared__ int wsum[32];
    __shared__ int cnt[N_GRAPHS];
    int t    = threadIdx.x;
    int wid  = t >> 5;
    int lane = t & 31;
    if (t < N_GRAPHS) cnt[t] = 0;
    __syncthreads();

    for (int n = t; n < N_NODES; n += T) {
        g_norm_src[n] = rsqrtf((float)max(g_deg_out[n], 1));
        g_norm_dst[n] = rsqrtf((float)max(g_deg_in [n], 1));
        atomicAdd(&cnt[gids[n]], 1);
    }

    int base = t * C;
    int local = 0;
    #pragma unroll
    for (int i = 0; i < C; i++) {
        int idx = base + i;
        if (idx < N_NODES) local += g_deg_in[idx];
    }
    // warp-level inclusive scan
    int v = local;
    #pragma unroll
    for (int off = 1; off < 32; off <<= 1) {
        int u = __shfl_up_sync(0xffffffffu, v, off);
        if (lane >= off) v += u;
    }
    if (lane == 31) wsum[wid] = v;
    __syncthreads();
    if (wid == 0) {
        int u = wsum[lane];
        #pragma unroll
        for (int off = 1; off < 32; off <<= 1) {
            int p = __shfl_up_sync(0xffffffffu, u, off);
            if (lane >= off) u += p;
        }
        wsum[lane] = u;
    }
    __syncthreads();
    int run = v - local + (wid > 0 ? wsum[wid - 1] : 0);   // exclusive prefix
    #pragma unroll
    for (int i = 0; i < C; i++) {
        int idx = base + i;
        if (idx < N_NODES) {
            g_row_ptr[idx] = run;
            g_cursor [idx] = run;
            run += g_deg_in[idx];
        }
    }
    if (t == T - 1) g_row_ptr[N_NODES] = run;

    if (t < N_GRAPHS) {
        g_gsum[t] = 0.f;
        g_ginv[t] = 1.f / fmaxf((float)cnt[t], 1.f);
    }
}

// ------- [2] scatter edges into CSR + prescale X to fp16 + convert W1/W2 to fp16 -------
#define TB 256
#define EDGE_BLOCKS ((N_EDGES + TB - 1) / TB)
#define XS_BLOCKS   ((N_NODES * (F / 4) + TB - 1) / TB)
#define W_BLOCKS    ((F * F / 4 + TB - 1) / TB)           // per matrix: 16 blocks

__global__ void k_scatter_scale(const int* __restrict__ src,
                                const int* __restrict__ dst,
                                const float* __restrict__ X,
                                const float* __restrict__ W1,
                                const float* __restrict__ W2) {
    int b = blockIdx.x;
    if (b < EDGE_BLOCKS) {
        int e = b * TB + threadIdx.x;
        if (e < N_EDGES) {
            int pos = atomicAdd(&g_cursor[dst[e]], 1);
            g_csr[pos] = src[e];
        }
    } else if (b < EDGE_BLOCKS + XS_BLOCKS) {
        int idx = (b - EDGE_BLOCKS) * TB + threadIdx.x;
        if (idx < N_NODES * (F / 4)) {
            float s = g_norm_src[idx >> 5];
            float4 v = ((const float4*)X)[idx];
            __half2 h0 = __floats2half2_rn(v.x * s, v.y * s);
            __half2 h1 = __floats2half2_rn(v.z * s, v.w * s);
            uint2 o;
            o.x = *(unsigned*)&h0;
            o.y = *(unsigned*)&h1;
            ((uint2*)g_xh)[idx] = o;
        }
    } else {
        int idx = (b - EDGE_BLOCKS - XS_BLOCKS) * TB + threadIdx.x;
        if (idx < 2 * (F * F / 4)) {                       // 8192 uint2 total
            int m = idx >= F * F / 4;                      // 0: W1, 1: W2
            int i = m ? idx - F * F / 4 : idx;
            float4 v = ((const float4*)(m ? W2 : W1))[i];
            __half2 h0 = __floats2half2_rn(v.x, v.y);
            __half2 h1 = __floats2half2_rn(v.z, v.w);
            uint2 o;
            o.x = *(unsigned*)&h0;
            o.y = *(unsigned*)&h1;
            ((uint2*)(m ? g_w2h : g_w1h))[i] = o;
        }
    }
}

// ------- [3]/[4] fused layer: fp16 gather + fp16-W fp32-acc GEMM (W amortized x2) -------
// 8 warps/block, each warp owns 2 nodes. Lane owns 4 output columns.
#define NPW   2
#define WARPS 8
#define NPB   (NPW * WARPS)             // 16 nodes per block

template <int LAYER>    // 1: read g_xh/g_w1h, write g_h1h; 2: read g_h1h/g_w2h, fused pool
__global__ __launch_bounds__(256) void k_layer(const float* __restrict__ b,
                                               const float* __restrict__ Wd,
                                               const int*  __restrict__ gids) {
    __shared__ float rowbuf[NPB][F];
    int w    = threadIdx.x >> 5;
    int lane = threadIdx.x & 31;
    int n0   = blockIdx.x * NPB + w * NPW;

    const uint2* X  = (const uint2*)(LAYER == 1 ? (const __half*)g_xh
                                                : (const __half*)g_h1h);
    const uint2* Wh = (const uint2*)(LAYER == 1 ? (const __half*)g_w1h
                                                : (const __half*)g_w2h);

    // ---- gather 2 nodes (8-deep MLP each) ----
    #pragma unroll
    for (int j = 0; j < NPW; j++) {
        int n = n0 + j;
        if (n >= N_NODES) break;
        int beg = g_row_ptr[n], end = g_row_ptr[n + 1];
        float ax = 0.f, ay = 0.f, az = 0.f, aw = 0.f;
        int e = beg;
        #define ACC(v) { \
            float2 f0 = __half22float2(*(__half2*)&(v).x); \
            float2 f1 = __half22float2(*(__half2*)&(v).y); \
            ax += f0.x; ay += f0.y; az += f1.x; aw += f1.y; }
        for (; e + 8 <= end; e += 8) {
            int s0 = g_csr[e+0], s1 = g_csr[e+1], s2 = g_csr[e+2], s3 = g_csr[e+3];
            int s4 = g_csr[e+4], s5 = g_csr[e+5], s6 = g_csr[e+6], s7 = g_csr[e+7];
            uint2 v0 = X[s0 * 32 + lane];
            uint2 v1 = X[s1 * 32 + lane];
            uint2 v2 = X[s2 * 32 + lane];
            uint2 v3 = X[s3 * 32 + lane];
            uint2 v4 = X[s4 * 32 + lane];
            uint2 v5 = X[s5 * 32 + lane];
            uint2 v6 = X[s6 * 32 + lane];
            uint2 v7 = X[s7 * 32 + lane];
            ACC(v0) ACC(v1) ACC(v2) ACC(v3) ACC(v4) ACC(v5) ACC(v6) ACC(v7)
        }
        for (; e < end; e++) {
            int s = g_csr[e];
            uint2 v = X[s * 32 + lane];
            ACC(v)
        }
        #undef ACC
        float nd = g_norm_dst[n];
        ((float4*)rowbuf[w * NPW + j])[lane] =
            make_float4(ax * nd, ay * nd, az * nd, aw * nd);
    }
    __syncwarp();

    // ---- GEMM: one fp16 W[k] load (uint2 = 4 cols) serves 2 nodes ----
    float4 bv = ((const float4*)b)[lane];
    float o0x = bv.x, o0y = bv.y, o0z = bv.z, o0w = bv.w;
    float o1x = bv.x, o1y = bv.y, o1z = bv.z, o1w = bv.w;
    const float* r0 = rowbuf[w * NPW + 0];
    const float* r1 = rowbuf[w * NPW + 1];
    #pragma unroll 8
    for (int k = 0; k < F; k++) {
        uint2 wv = Wh[k * 32 + lane];                    // LDG.64, L1-resident
        float2 w01 = __half22float2(*(__half2*)&wv.x);
        float2 w23 = __half22float2(*(__half2*)&wv.y);
        float a0 = r0[k], a1 = r1[k];                    // LDS broadcasts
        o0x += a0 * w01.x; o0y += a0 * w01.y; o0z += a0 * w23.x; o0w += a0 * w23.y;
        o1x += a1 * w01.x; o1y += a1 * w01.y; o1z += a1 * w23.x; o1w += a1 * w23.y;
    }

    // ---- epilogue per node ----
    #pragma unroll
    for (int j = 0; j < NPW; j++) {
        int n = n0 + j;
        if (n >= N_NODES) break;
        float ox = j == 0 ? o0x : o1x;
        float oy = j == 0 ? o0y : o1y;
        float oz = j == 0 ? o0z : o1z;
        float ow = j == 0 ? o0w : o1w;
        ox = fmaxf(ox, 0.f); oy = fmaxf(oy, 0.f);
        oz = fmaxf(oz, 0.f); ow = fmaxf(ow, 0.f);

        if (LAYER == 1) {
            float ns = g_norm_src[n];
            __half2 h0 = __floats2half2_rn(ox * ns, oy * ns);
            __half2 h1 = __floats2half2_rn(oz * ns, ow * ns);
            uint2 o;
            o.x = *(unsigned*)&h0;
            o.y = *(unsigned*)&h1;
            ((uint2*)g_h1h)[n * 32 + lane] = o;
        } else {
            float4 wd = ((const float4*)Wd)[lane];
            float z = ox * wd.x + oy * wd.y + oz * wd.z + ow * wd.w;
            #pragma unroll
            for (int off = 16; off > 0; off >>= 1)
                z += __shfl_xor_sync(0xffffffffu, z, off);
            if (lane == 0) atomicAdd(&g_gsum[gids[n]], z);
        }
    }
}

// ---------------- [5] readout + re-zero degree arrays for next run ----------------
__global__ void k_final(const float* __restrict__ bd, float* __restrict__ out) {
    int i = blockIdx.x * blockDim.x + threadIdx.x;
    if (i < N_NODES) { g_deg_out[i] = 0; g_deg_in[i] = 0; }
    if (i < N_GRAPHS) out[i] = g_gsum[i] * g_ginv[i] + bd[0];
}

// ---------------- launch ----------------
extern "C" void kernel_launch(void* const* d_in, const int* in_sizes, int n_in,
                              void* d_out, int out_size) {
    const float* in_feat = (const float*)d_in[0];
    const int*   src     = (const int*)  d_in[1];
    const int*   dst     = (const int*)  d_in[2];
    const int*   gids    = (const int*)  d_in[3];
    const float* W1      = (const float*)d_in[4];
    const float* b1      = (const float*)d_in[5];
    const float* W2      = (const float*)d_in[6];
    const float* b2      = (const float*)d_in[7];
    const float* Wd      = (const float*)d_in[8];
    const float* bd      = (const float*)d_in[9];
    float* out = (float*)d_out;

    int layerBlocks = (N_NODES + NPB - 1) / NPB;     // 625
    int finalBlocks = (N_NODES + TB - 1) / TB;
    int ssBlocks    = EDGE_BLOCKS + XS_BLOCKS + 2 * W_BLOCKS;

    k_degree        <<<EDGE_BLOCKS, TB>>>(src, dst);                      // 0
    k_prep          <<<1, 1024>>>(gids);                                  // 1
    k_scatter_scale <<<ssBlocks, TB>>>(src, dst, in_feat, W1, W2);        // 2
    k_layer<1>      <<<layerBlocks, TB>>>(b1, nullptr, nullptr);          // 3  (ncu slot)
    k_layer<2>      <<<layerBlocks, TB>>>(b2, Wd, gids);                  // 4
    k_final         <<<finalBlocks, TB>>>(bd, out);                       // 5
}